// round 1
// baseline (speedup 1.0000x reference)
#include <cuda_runtime.h>
#include <math_constants.h>

#define BATCH 64

// ping-pong scratch (max activation: 64 x 128 x 128 floats = 4 MB each)
__device__ float g_bufA[BATCH * 128 * 128];
__device__ float g_bufB[BATCH * 128 * 128];

// ---------------------------------------------------------------------------
// Locally-connected conv (stride 1) + bias + ReLU.
// out[b,i,j] = relu( sum_{u,v} in[b, i-pad+u, j-pad+v] * w[i,j,u,v] + bias[i,j] )
// One thread per output element. Weights for a position are contiguous (K*K).
// ---------------------------------------------------------------------------
template <int K>
__global__ void lc_relu_kernel(const float* __restrict__ in,
                               const float* __restrict__ w,
                               const float* __restrict__ bias,
                               float* __restrict__ out,
                               int H, int W, int pad) {
    int idx = blockIdx.x * blockDim.x + threadIdx.x;
    int total = BATCH * H * W;
    if (idx >= total) return;
    int j = idx % W;
    int i = (idx / W) % H;
    int b = idx / (W * H);

    const float* wp = w + (i * W + j) * K * K;
    const float* ip = in + b * H * W;
    float acc = __ldg(bias + i * W + j);

#pragma unroll
    for (int u = 0; u < K; ++u) {
        int ii = i + u - pad;
        if (ii < 0 || ii >= H) continue;
#pragma unroll
        for (int v = 0; v < K; ++v) {
            int jj = j + v - pad;
            if (jj < 0 || jj >= W) continue;
            acc = fmaf(__ldg(ip + ii * W + jj), __ldg(wp + u * K + v), acc);
        }
    }
    out[idx] = fmaxf(acc, 0.0f);
}

// ---------------------------------------------------------------------------
// LayerNorm over the full spatial map of one sample (+ optional 2x2 maxpool).
// One block per batch sample. Deterministic fixed-tree reduction.
// ---------------------------------------------------------------------------
template <bool POOL>
__global__ void ln_kernel(const float* __restrict__ in,
                          const float* __restrict__ g,
                          const float* __restrict__ be,
                          float* __restrict__ out,
                          int H, int W) {
    const int b = blockIdx.x;
    const int N = H * W;
    const float* ip = in + b * N;

    float s = 0.0f, ss = 0.0f;
    for (int i = threadIdx.x; i < N; i += blockDim.x) {
        float v = ip[i];
        s += v;
        ss += v * v;
    }
    __shared__ float red0[32];
    __shared__ float red1[32];
#pragma unroll
    for (int o = 16; o; o >>= 1) {
        s += __shfl_down_sync(0xFFFFFFFFu, s, o);
        ss += __shfl_down_sync(0xFFFFFFFFu, ss, o);
    }
    int wid = threadIdx.x >> 5, lid = threadIdx.x & 31;
    if (lid == 0) { red0[wid] = s; red1[wid] = ss; }
    __syncthreads();
    int nw = blockDim.x >> 5;
    if (wid == 0) {
        s = (lid < nw) ? red0[lid] : 0.0f;
        ss = (lid < nw) ? red1[lid] : 0.0f;
#pragma unroll
        for (int o = 16; o; o >>= 1) {
            s += __shfl_down_sync(0xFFFFFFFFu, s, o);
            ss += __shfl_down_sync(0xFFFFFFFFu, ss, o);
        }
        if (lid == 0) { red0[0] = s; red1[0] = ss; }
    }
    __syncthreads();
    float inv_n = 1.0f / (float)N;
    float mu = red0[0] * inv_n;
    float var = red1[0] * inv_n - mu * mu;
    float rstd = rsqrtf(var + 1e-5f);

    if (POOL) {
        int Hp = H >> 1, Wp = W >> 1;
        int Np = Hp * Wp;
        for (int p = threadIdx.x; p < Np; p += blockDim.x) {
            int jo = p % Wp, io = p / Wp;
            float m = -CUDART_INF_F;
#pragma unroll
            for (int di = 0; di < 2; ++di)
#pragma unroll
                for (int dj = 0; dj < 2; ++dj) {
                    int i = 2 * io + di, j = 2 * jo + dj;
                    int q = i * W + j;
                    float v = (ip[q] - mu) * rstd * __ldg(g + q) + __ldg(be + q);
                    m = fmaxf(m, v);
                }
            out[b * Np + p] = m;
        }
    } else {
        for (int p = threadIdx.x; p < N; p += blockDim.x) {
            out[b * N + p] = (ip[p] - mu) * rstd * __ldg(g + p) + __ldg(be + p);
        }
    }
}

// ---------------------------------------------------------------------------
// FC (h[64,256] @ fcw.T[256,1024] + fcb) + softmax over 1024.
// One block (256 threads, 8 warps) per batch row; warp-per-output dot with
// coalesced fcw reads, then block softmax.
// ---------------------------------------------------------------------------
__global__ void fc_softmax_kernel(const float* __restrict__ h,
                                  const float* __restrict__ fcw,
                                  const float* __restrict__ fcb,
                                  float* __restrict__ out) {
    const int b = blockIdx.x;
    const int tid = threadIdx.x;       // 256 threads
    const int wid = tid >> 5, lid = tid & 31;

    __shared__ float hs[256];
    __shared__ float logits[1024];
    __shared__ float red[8];

    hs[tid] = h[b * 256 + tid];
    __syncthreads();

    // each warp computes outputs o = wid, wid+8, ..., 1024 total
    for (int o = wid; o < 1024; o += 8) {
        const float* wr = fcw + o * 256;
        float sdot = 0.0f;
#pragma unroll
        for (int k = lid; k < 256; k += 32) sdot = fmaf(hs[k], __ldg(wr + k), sdot);
#pragma unroll
        for (int off = 16; off; off >>= 1) sdot += __shfl_down_sync(0xFFFFFFFFu, sdot, off);
        if (lid == 0) logits[o] = sdot + __ldg(fcb + o);
    }
    __syncthreads();

    // max
    float mx = -CUDART_INF_F;
    for (int i = tid; i < 1024; i += 256) mx = fmaxf(mx, logits[i]);
#pragma unroll
    for (int off = 16; off; off >>= 1) mx = fmaxf(mx, __shfl_xor_sync(0xFFFFFFFFu, mx, off));
    if (lid == 0) red[wid] = mx;
    __syncthreads();
    mx = red[0];
#pragma unroll
    for (int w = 1; w < 8; ++w) mx = fmaxf(mx, red[w]);
    __syncthreads();

    // exp + sum
    float ps = 0.0f;
    for (int i = tid; i < 1024; i += 256) {
        float e = __expf(logits[i] - mx);
        logits[i] = e;
        ps += e;
    }
#pragma unroll
    for (int off = 16; off; off >>= 1) ps += __shfl_xor_sync(0xFFFFFFFFu, ps, off);
    if (lid == 0) red[wid] = ps;
    __syncthreads();
    float tot = red[0];
#pragma unroll
    for (int w = 1; w < 8; ++w) tot += red[w];
    float inv = 1.0f / tot;

    for (int i = tid; i < 1024; i += 256) out[b * 1024 + i] = logits[i] * inv;
}

// ---------------------------------------------------------------------------
extern "C" void kernel_launch(void* const* d_in, const int* in_sizes, int n_in,
                              void* d_out, int out_size) {
    (void)in_sizes; (void)n_in; (void)out_size;

    const float* x = (const float*)d_in[0];
    // per-layer params: w at 1+4*(L-1), b at +1, g at +2, be at +3
    const float* w[7];
    const float* bi[7];
    const float* gg[7];
    const float* bb[7];
    for (int L = 1; L <= 6; ++L) {
        w[L]  = (const float*)d_in[1 + 4 * (L - 1) + 0];
        bi[L] = (const float*)d_in[1 + 4 * (L - 1) + 1];
        gg[L] = (const float*)d_in[1 + 4 * (L - 1) + 2];
        bb[L] = (const float*)d_in[1 + 4 * (L - 1) + 3];
    }
    const float* fcw = (const float*)d_in[25];
    const float* fcb = (const float*)d_in[26];
    float* out = (float*)d_out;

    float* bufA = nullptr;
    float* bufB = nullptr;
    cudaGetSymbolAddress((void**)&bufA, g_bufA);
    cudaGetSymbolAddress((void**)&bufB, g_bufB);

    const int T = 256;
    auto blocks = [](int n, int t) { return (n + t - 1) / t; };

    // L1: 128x128, K=7 pad=3 -> relu -> LN -> pool -> 64x64
    lc_relu_kernel<7><<<blocks(BATCH * 128 * 128, T), T>>>(x, w[1], bi[1], bufA, 128, 128, 3);
    ln_kernel<true><<<BATCH, T>>>(bufA, gg[1], bb[1], bufB, 128, 128);

    // L2: 64x64, K=5 pad=2 -> relu -> LN
    lc_relu_kernel<5><<<blocks(BATCH * 64 * 64, T), T>>>(bufB, w[2], bi[2], bufA, 64, 64, 2);
    ln_kernel<false><<<BATCH, T>>>(bufA, gg[2], bb[2], bufB, 64, 64);

    // L3: 64x64, K=5 pad=2 -> relu -> LN -> pool -> 32x32
    lc_relu_kernel<5><<<blocks(BATCH * 64 * 64, T), T>>>(bufB, w[3], bi[3], bufA, 64, 64, 2);
    ln_kernel<true><<<BATCH, T>>>(bufA, gg[3], bb[3], bufB, 64, 64);

    // L4: 32x32, K=3 pad=1 -> relu -> LN
    lc_relu_kernel<3><<<blocks(BATCH * 32 * 32, T), T>>>(bufB, w[4], bi[4], bufA, 32, 32, 1);
    ln_kernel<false><<<BATCH, T>>>(bufA, gg[4], bb[4], bufB, 32, 32);

    // L5: 32x32, K=3 pad=1 -> relu -> LN -> pool -> 16x16
    lc_relu_kernel<3><<<blocks(BATCH * 32 * 32, T), T>>>(bufB, w[5], bi[5], bufA, 32, 32, 1);
    ln_kernel<true><<<BATCH, T>>>(bufA, gg[5], bb[5], bufB, 32, 32);

    // L6: 16x16, K=3 pad=1 -> relu -> LN
    lc_relu_kernel<3><<<blocks(BATCH * 16 * 16, T), T>>>(bufB, w[6], bi[6], bufA, 16, 16, 1);
    ln_kernel<false><<<BATCH, T>>>(bufA, gg[6], bb[6], bufB, 16, 16);

    // FC + softmax: bufB is [64, 256] flattened
    fc_softmax_kernel<<<BATCH, T>>>(bufB, fcw, fcb, out);
}

// round 2
// speedup vs baseline: 2.3071x; 2.3071x over previous
#include <cuda_runtime.h>
#include <math_constants.h>

#define BATCH 64

// scratch
__device__ float g_conv1[BATCH * 128 * 128];   // conv1 output (post-relu)
__device__ float g_h[BATCH * 256];             // flattened features before FC
__device__ float g_logits[BATCH * 1024];       // FC logits
__device__ float g_wpack[1141760];             // padded/vec4-aligned weights

// packed-weight offsets (floats)
#define OFF_W1 0          // 16384 pos * 52
#define OFF_W2 851968     // 4096 * 32
#define OFF_W3 983040     // 4096 * 32
#define OFF_W4 1114112    // 1024 * 12
#define OFF_W5 1126400    // 1024 * 12
#define OFF_W6 1138688    // 256 * 12

// ---------------------------------------------------------------------------
// Repack weights: pad each position's K*K weights to a 16B-aligned stride so
// conv kernels can use float4 loads.
// ---------------------------------------------------------------------------
__global__ void repack_kernel(const float* __restrict__ w1, const float* __restrict__ w2,
                              const float* __restrict__ w3, const float* __restrict__ w4,
                              const float* __restrict__ w5, const float* __restrict__ w6,
                              float* __restrict__ wp) {
    int tid = blockIdx.x * blockDim.x + threadIdx.x;
    int nt = gridDim.x * blockDim.x;
    for (int i = tid; i < 16384 * 49; i += nt) { int p = i / 49, k = i - p * 49; wp[OFF_W1 + p * 52 + k] = w1[i]; }
    for (int i = tid; i < 4096 * 25; i += nt)  { int p = i / 25, k = i - p * 25; wp[OFF_W2 + p * 32 + k] = w2[i]; }
    for (int i = tid; i < 4096 * 25; i += nt)  { int p = i / 25, k = i - p * 25; wp[OFF_W3 + p * 32 + k] = w3[i]; }
    for (int i = tid; i < 1024 * 9; i += nt)   { int p = i / 9,  k = i - p * 9;  wp[OFF_W4 + p * 12 + k] = w4[i]; }
    for (int i = tid; i < 1024 * 9; i += nt)   { int p = i / 9,  k = i - p * 9;  wp[OFF_W5 + p * 12 + k] = w5[i]; }
    for (int i = tid; i < 256 * 9; i += nt)    { int p = i / 9,  k = i - p * 9;  wp[OFF_W6 + p * 12 + k] = w6[i]; }
}

// ---------------------------------------------------------------------------
// Conv1: 128x128, K=7, pad=3, locally-connected, + ReLU.
// Block = 8x32 position tile x 8-batch group. Weights (52 floats as 13 float4)
// held in registers and reused across 8 batches; inputs in zero-padded smem.
// Grid: (64 tiles, 8 batch groups), 256 threads.
// ---------------------------------------------------------------------------
__global__ void __launch_bounds__(256) conv1_kernel(const float* __restrict__ x,
                                                    const float* __restrict__ wp,
                                                    const float* __restrict__ b1,
                                                    float* __restrict__ out) {
    __shared__ float sm[8][14][38];   // 8 batches x (8+6) x (32+6)
    const int tile = blockIdx.x;
    const int bg = blockIdx.y;
    const int tx = tile & 3, ty = tile >> 2;
    const int tj0 = tx * 32, ti0 = ty * 8;
    const int tid = threadIdx.x;

    // load input tile (zero-padded halo)
    for (int e = tid; e < 8 * 14 * 38; e += 256) {
        int bb = e / (14 * 38);
        int rem = e - bb * (14 * 38);
        int r = rem / 38, c = rem - r * 38;
        int gi = ti0 - 3 + r, gj = tj0 - 3 + c;
        float v = 0.0f;
        if ((unsigned)gi < 128u && (unsigned)gj < 128u)
            v = x[(bg * 8 + bb) * 16384 + gi * 128 + gj];
        sm[bb][r][c] = v;
    }

    const int ti = tid >> 5, tj = tid & 31;      // thread -> position in tile
    const int p = (ti0 + ti) * 128 + (tj0 + tj); // global position
    float4 wreg[13];
    const float4* wv = (const float4*)(wp + OFF_W1 + p * 52);
#pragma unroll
    for (int t = 0; t < 13; ++t) wreg[t] = __ldg(wv + t);
    const float* wf = (const float*)wreg;
    const float bias = __ldg(b1 + p);
    __syncthreads();

    for (int bb = 0; bb < 8; ++bb) {
        float acc = bias;
#pragma unroll
        for (int u = 0; u < 7; ++u)
#pragma unroll
            for (int v = 0; v < 7; ++v)
                acc = fmaf(sm[bb][ti + u][tj + v], wf[u * 7 + v], acc);
        out[(bg * 8 + bb) * 16384 + p] = fmaxf(acc, 0.0f);
    }
}

// ---------------------------------------------------------------------------
// Mega kernel pieces
// ---------------------------------------------------------------------------
__device__ __forceinline__ float2 block_stats2(float s, float ss) {
    __shared__ float r0[16], r1[16];
    int tid = threadIdx.x, wid = tid >> 5, lid = tid & 31;
#pragma unroll
    for (int o = 16; o; o >>= 1) {
        s += __shfl_down_sync(0xFFFFFFFFu, s, o);
        ss += __shfl_down_sync(0xFFFFFFFFu, ss, o);
    }
    if (lid == 0) { r0[wid] = s; r1[wid] = ss; }
    __syncthreads();
    if (wid == 0) {
        s = (lid < 16) ? r0[lid] : 0.0f;
        ss = (lid < 16) ? r1[lid] : 0.0f;
#pragma unroll
        for (int o = 8; o; o >>= 1) {
            s += __shfl_down_sync(0xFFFFFFFFu, s, o);
            ss += __shfl_down_sync(0xFFFFFFFFu, ss, o);
        }
        if (lid == 0) { r0[0] = s; r1[0] = ss; }
    }
    __syncthreads();
    float2 res = make_float2(r0[0], r1[0]);
    __syncthreads();
    return res;
}

// locally-connected conv + relu from smem src to smem dst; weights vec4-packed
template <int H, int K, int PAD, int WS>
__device__ __forceinline__ void conv_stage(const float* __restrict__ src, float* __restrict__ dst,
                                           const float* __restrict__ wp, const float* __restrict__ bias) {
    constexpr int N = H * H;
    constexpr int NV = (K * K + 3) / 4;
    for (int p = threadIdx.x; p < N; p += 512) {
        int i = p / H, j = p - i * H;
        float4 wreg[NV];
        const float4* wv = (const float4*)(wp + p * WS);
#pragma unroll
        for (int t = 0; t < NV; ++t) wreg[t] = __ldg(wv + t);
        const float* wf = (const float*)wreg;
        float acc = __ldg(bias + p);
#pragma unroll
        for (int u = 0; u < K; ++u) {
            int ii = i + u - PAD;
            if ((unsigned)ii < (unsigned)H) {
#pragma unroll
                for (int v = 0; v < K; ++v) {
                    int jj = j + v - PAD;
                    float xv = ((unsigned)jj < (unsigned)H) ? src[ii * H + jj] : 0.0f;
                    acc = fmaf(xv, wf[u * K + v], acc);
                }
            }
        }
        dst[p] = fmaxf(acc, 0.0f);
    }
}

// ---------------------------------------------------------------------------
// Mega kernel: block per sample (grid=64, 512 threads).
// LN1+pool (from conv1 global) -> conv2 -> LN2 -> conv3 -> LN3+pool
// -> conv4 -> LN4 -> conv5 -> LN5+pool -> conv6 -> LN6 -> h[256]
// ---------------------------------------------------------------------------
__global__ void __launch_bounds__(512) mega_kernel(
    const float* __restrict__ c1, const float* __restrict__ g1, const float* __restrict__ be1,
    const float* __restrict__ wp,
    const float* __restrict__ b2, const float* __restrict__ g2, const float* __restrict__ be2,
    const float* __restrict__ b3, const float* __restrict__ g3, const float* __restrict__ be3,
    const float* __restrict__ b4, const float* __restrict__ g4, const float* __restrict__ be4,
    const float* __restrict__ b5, const float* __restrict__ g5, const float* __restrict__ be5,
    const float* __restrict__ b6, const float* __restrict__ g6, const float* __restrict__ be6,
    float* __restrict__ hout) {
    __shared__ float A[4096], B[4096];
    const int tid = threadIdx.x;
    const int b = blockIdx.x;
    const float* ip = c1 + b * 16384;

    // --- LN1 stats over conv1 output (128x128) ---
    float s = 0.0f, ss = 0.0f;
    for (int i = tid; i < 16384; i += 512) { float v = ip[i]; s += v; ss += v * v; }
    float2 st = block_stats2(s, ss);
    float mu = st.x * (1.0f / 16384.0f);
    float rstd = rsqrtf(st.y * (1.0f / 16384.0f) - mu * mu + 1e-5f);
    // normalize + 2x2 pool -> A (64x64)
    for (int p = tid; p < 4096; p += 512) {
        int io = p >> 6, jo = p & 63;
        float m = -CUDART_INF_F;
#pragma unroll
        for (int di = 0; di < 2; ++di)
#pragma unroll
            for (int dj = 0; dj < 2; ++dj) {
                int q = (2 * io + di) * 128 + 2 * jo + dj;
                float v = (ip[q] - mu) * rstd * __ldg(g1 + q) + __ldg(be1 + q);
                m = fmaxf(m, v);
            }
        A[p] = m;
    }
    __syncthreads();

    // --- conv2 (64x64, K=5) A -> B ---
    conv_stage<64, 5, 2, 32>(A, B, wp + OFF_W2, b2);
    __syncthreads();
    // --- LN2 in-place on B ---
    s = ss = 0.0f;
    for (int p = tid; p < 4096; p += 512) { float v = B[p]; s += v; ss += v * v; }
    st = block_stats2(s, ss);
    mu = st.x * (1.0f / 4096.0f);
    rstd = rsqrtf(st.y * (1.0f / 4096.0f) - mu * mu + 1e-5f);
    for (int p = tid; p < 4096; p += 512) B[p] = (B[p] - mu) * rstd * __ldg(g2 + p) + __ldg(be2 + p);
    __syncthreads();

    // --- conv3 (64x64, K=5) B -> A ---
    conv_stage<64, 5, 2, 32>(B, A, wp + OFF_W3, b3);
    __syncthreads();
    // --- LN3 + pool: A (64x64) -> B (32x32) ---
    s = ss = 0.0f;
    for (int p = tid; p < 4096; p += 512) { float v = A[p]; s += v; ss += v * v; }
    st = block_stats2(s, ss);
    mu = st.x * (1.0f / 4096.0f);
    rstd = rsqrtf(st.y * (1.0f / 4096.0f) - mu * mu + 1e-5f);
    for (int p = tid; p < 1024; p += 512) {
        int io = p >> 5, jo = p & 31;
        float m = -CUDART_INF_F;
#pragma unroll
        for (int di = 0; di < 2; ++di)
#pragma unroll
            for (int dj = 0; dj < 2; ++dj) {
                int q = (2 * io + di) * 64 + 2 * jo + dj;
                float v = (A[q] - mu) * rstd * __ldg(g3 + q) + __ldg(be3 + q);
                m = fmaxf(m, v);
            }
        B[p] = m;
    }
    __syncthreads();

    // --- conv4 (32x32, K=3) B -> A ---
    conv_stage<32, 3, 1, 12>(B, A, wp + OFF_W4, b4);
    __syncthreads();
    // --- LN4 in-place on A (1024) ---
    s = ss = 0.0f;
    for (int p = tid; p < 1024; p += 512) { float v = A[p]; s += v; ss += v * v; }
    st = block_stats2(s, ss);
    mu = st.x * (1.0f / 1024.0f);
    rstd = rsqrtf(st.y * (1.0f / 1024.0f) - mu * mu + 1e-5f);
    for (int p = tid; p < 1024; p += 512) A[p] = (A[p] - mu) * rstd * __ldg(g4 + p) + __ldg(be4 + p);
    __syncthreads();

    // --- conv5 (32x32, K=3) A -> B ---
    conv_stage<32, 3, 1, 12>(A, B, wp + OFF_W5, b5);
    __syncthreads();
    // --- LN5 + pool: B (32x32) -> A (16x16) ---
    s = ss = 0.0f;
    for (int p = tid; p < 1024; p += 512) { float v = B[p]; s += v; ss += v * v; }
    st = block_stats2(s, ss);
    mu = st.x * (1.0f / 1024.0f);
    rstd = rsqrtf(st.y * (1.0f / 1024.0f) - mu * mu + 1e-5f);
    for (int p = tid; p < 256; p += 512) {
        int io = p >> 4, jo = p & 15;
        float m = -CUDART_INF_F;
#pragma unroll
        for (int di = 0; di < 2; ++di)
#pragma unroll
            for (int dj = 0; dj < 2; ++dj) {
                int q = (2 * io + di) * 32 + 2 * jo + dj;
                float v = (B[q] - mu) * rstd * __ldg(g5 + q) + __ldg(be5 + q);
                m = fmaxf(m, v);
            }
        A[p] = m;
    }
    __syncthreads();

    // --- conv6 (16x16, K=3) A -> B ---
    conv_stage<16, 3, 1, 12>(A, B, wp + OFF_W6, b6);
    __syncthreads();
    // --- LN6 over B (256) -> h ---
    s = ss = 0.0f;
    for (int p = tid; p < 256; p += 512) { float v = B[p]; s += v; ss += v * v; }
    st = block_stats2(s, ss);
    mu = st.x * (1.0f / 256.0f);
    rstd = rsqrtf(st.y * (1.0f / 256.0f) - mu * mu + 1e-5f);
    for (int p = tid; p < 256; p += 512)
        hout[b * 256 + p] = (B[p] - mu) * rstd * __ldg(g6 + p) + __ldg(be6 + p);
}

// ---------------------------------------------------------------------------
// FC: logits[64,1024] = h[64,256] @ fcw.T + fcb.
// Grid = (8 col-tiles of 128 outputs, 8 row-groups of 8 rows), 256 threads.
// Warp per output with h cached in registers; fcw read coalesced as float4.
// ---------------------------------------------------------------------------
__global__ void __launch_bounds__(256) fc_kernel(const float* __restrict__ h,
                                                 const float* __restrict__ fcw,
                                                 const float* __restrict__ fcb,
                                                 float* __restrict__ logits) {
    __shared__ float hs[8 * 256];
    const int ct = blockIdx.x, rg = blockIdx.y;
    const int tid = threadIdx.x, wid = tid >> 5, lid = tid & 31;

    for (int e = tid; e < 2048; e += 256) hs[e] = h[rg * 2048 + e];
    __syncthreads();

    float hr[8][8];
#pragma unroll
    for (int r = 0; r < 8; ++r)
#pragma unroll
        for (int c = 0; c < 8; ++c) hr[r][c] = hs[r * 256 + lid * 8 + c];

    const int obase = ct * 128 + wid * 16;
    for (int t = 0; t < 16; ++t) {
        int o = obase + t;
        const float4* wr = (const float4*)(fcw + o * 256 + lid * 8);
        float4 wa = __ldg(wr), wb = __ldg(wr + 1);
        float a[8];
#pragma unroll
        for (int r = 0; r < 8; ++r) {
            a[r] = hr[r][0] * wa.x + hr[r][1] * wa.y + hr[r][2] * wa.z + hr[r][3] * wa.w
                 + hr[r][4] * wb.x + hr[r][5] * wb.y + hr[r][6] * wb.z + hr[r][7] * wb.w;
        }
#pragma unroll
        for (int r = 0; r < 8; ++r)
#pragma unroll
            for (int off = 16; off; off >>= 1) a[r] += __shfl_down_sync(0xFFFFFFFFu, a[r], off);
        if (lid == 0) {
            float bo = __ldg(fcb + o);
#pragma unroll
            for (int r = 0; r < 8; ++r) logits[(rg * 8 + r) * 1024 + o] = a[r] + bo;
        }
    }
}

// ---------------------------------------------------------------------------
// Softmax over 1024 per row. Grid=64, 256 threads.
// ---------------------------------------------------------------------------
__global__ void __launch_bounds__(256) softmax_kernel(const float* __restrict__ logits,
                                                      float* __restrict__ out) {
    __shared__ float sm[1024];
    __shared__ float red[8];
    const int b = blockIdx.x, tid = threadIdx.x, wid = tid >> 5, lid = tid & 31;
    const float* row = logits + b * 1024;

    float mx = -CUDART_INF_F;
    for (int i = tid; i < 1024; i += 256) { float v = row[i]; sm[i] = v; mx = fmaxf(mx, v); }
#pragma unroll
    for (int o = 16; o; o >>= 1) mx = fmaxf(mx, __shfl_xor_sync(0xFFFFFFFFu, mx, o));
    if (lid == 0) red[wid] = mx;
    __syncthreads();
    mx = red[0];
#pragma unroll
    for (int w = 1; w < 8; ++w) mx = fmaxf(mx, red[w]);

    float ps = 0.0f;
    for (int i = tid; i < 1024; i += 256) { float e = __expf(sm[i] - mx); sm[i] = e; ps += e; }
#pragma unroll
    for (int o = 16; o; o >>= 1) ps += __shfl_xor_sync(0xFFFFFFFFu, ps, o);
    __syncthreads();
    if (lid == 0) red[wid] = ps;
    __syncthreads();
    float tot = 0.0f;
#pragma unroll
    for (int w = 0; w < 8; ++w) tot += red[w];
    float inv = 1.0f / tot;
    for (int i = tid; i < 1024; i += 256) out[b * 1024 + i] = sm[i] * inv;
}

// ---------------------------------------------------------------------------
extern "C" void kernel_launch(void* const* d_in, const int* in_sizes, int n_in,
                              void* d_out, int out_size) {
    (void)in_sizes; (void)n_in; (void)out_size;

    const float* x = (const float*)d_in[0];
    const float* w[7];
    const float* bi[7];
    const float* gg[7];
    const float* bb[7];
    for (int L = 1; L <= 6; ++L) {
        w[L]  = (const float*)d_in[1 + 4 * (L - 1) + 0];
        bi[L] = (const float*)d_in[1 + 4 * (L - 1) + 1];
        gg[L] = (const float*)d_in[1 + 4 * (L - 1) + 2];
        bb[L] = (const float*)d_in[1 + 4 * (L - 1) + 3];
    }
    const float* fcw = (const float*)d_in[25];
    const float* fcb = (const float*)d_in[26];
    float* out = (float*)d_out;

    float *c1, *h, *lg, *wp;
    cudaGetSymbolAddress((void**)&c1, g_conv1);
    cudaGetSymbolAddress((void**)&h, g_h);
    cudaGetSymbolAddress((void**)&lg, g_logits);
    cudaGetSymbolAddress((void**)&wp, g_wpack);

    repack_kernel<<<256, 256>>>(w[1], w[2], w[3], w[4], w[5], w[6], wp);
    conv1_kernel<<<dim3(64, 8), 256>>>(x, wp, bi[1], c1);
    mega_kernel<<<64, 512>>>(c1, gg[1], bb[1], wp,
                             bi[2], gg[2], bb[2],
                             bi[3], gg[3], bb[3],
                             bi[4], gg[4], bb[4],
                             bi[5], gg[5], bb[5],
                             bi[6], gg[6], bb[6],
                             h);
    fc_kernel<<<dim3(8, 8), 256>>>(h, fcw, fcb, lg);
    softmax_kernel<<<64, 256>>>(lg, out);
}

// round 3
// speedup vs baseline: 2.3963x; 1.0386x over previous
#include <cuda_runtime.h>
#include <math_constants.h>

#define BATCH 64

// scratch
__device__ float g_conv1[BATCH * 128 * 128];   // conv1 output (post-relu)
__device__ float g_h[BATCH * 256];             // flattened features before FC
__device__ float g_logits[BATCH * 1024];       // FC logits
__device__ float g_wpack[1141760];             // padded/vec4-aligned weights

// packed-weight offsets (floats)
#define OFF_W1 0          // 16384 pos * 52
#define OFF_W2 851968     // 4096 * 32
#define OFF_W3 983040     // 4096 * 32
#define OFF_W4 1114112    // 1024 * 12
#define OFF_W5 1126400    // 1024 * 12
#define OFF_W6 1138688    // 256 * 12

// ---------------------------------------------------------------------------
// Repack weights: pad each position's K*K weights to a 16B-aligned stride so
// conv kernels can use float4 loads.
// ---------------------------------------------------------------------------
__global__ void repack_kernel(const float* __restrict__ w1, const float* __restrict__ w2,
                              const float* __restrict__ w3, const float* __restrict__ w4,
                              const float* __restrict__ w5, const float* __restrict__ w6,
                              float* __restrict__ wp) {
    int tid = blockIdx.x * blockDim.x + threadIdx.x;
    int nt = gridDim.x * blockDim.x;
    for (int i = tid; i < 16384 * 49; i += nt) { int p = i / 49, k = i - p * 49; wp[OFF_W1 + p * 52 + k] = w1[i]; }
    for (int i = tid; i < 4096 * 25; i += nt)  { int p = i / 25, k = i - p * 25; wp[OFF_W2 + p * 32 + k] = w2[i]; }
    for (int i = tid; i < 4096 * 25; i += nt)  { int p = i / 25, k = i - p * 25; wp[OFF_W3 + p * 32 + k] = w3[i]; }
    for (int i = tid; i < 1024 * 9; i += nt)   { int p = i / 9,  k = i - p * 9;  wp[OFF_W4 + p * 12 + k] = w4[i]; }
    for (int i = tid; i < 1024 * 9; i += nt)   { int p = i / 9,  k = i - p * 9;  wp[OFF_W5 + p * 12 + k] = w5[i]; }
    for (int i = tid; i < 256 * 9; i += nt)    { int p = i / 9,  k = i - p * 9;  wp[OFF_W6 + p * 12 + k] = w6[i]; }
}

// ---------------------------------------------------------------------------
// Conv1: 128x128, K=7, pad=3, locally-connected, + ReLU.
// Block = 8x32 position tile x 8-batch group. Weights (52 floats as 13 float4)
// held in registers and reused across 8 batches; inputs in zero-padded smem.
// Grid: (64 tiles, 8 batch groups), 256 threads.
// ---------------------------------------------------------------------------
__global__ void __launch_bounds__(256) conv1_kernel(const float* __restrict__ x,
                                                    const float* __restrict__ wp,
                                                    const float* __restrict__ b1,
                                                    float* __restrict__ out) {
    __shared__ float sm[8][14][38];   // 8 batches x (8+6) x (32+6)
    const int tile = blockIdx.x;
    const int bg = blockIdx.y;
    const int tx = tile & 3, ty = tile >> 2;
    const int tj0 = tx * 32, ti0 = ty * 8;
    const int tid = threadIdx.x;

    // load input tile (zero-padded halo)
    for (int e = tid; e < 8 * 14 * 38; e += 256) {
        int bb = e / (14 * 38);
        int rem = e - bb * (14 * 38);
        int r = rem / 38, c = rem - r * 38;
        int gi = ti0 - 3 + r, gj = tj0 - 3 + c;
        float v = 0.0f;
        if ((unsigned)gi < 128u && (unsigned)gj < 128u)
            v = x[(bg * 8 + bb) * 16384 + gi * 128 + gj];
        sm[bb][r][c] = v;
    }

    const int ti = tid >> 5, tj = tid & 31;      // thread -> position in tile
    const int p = (ti0 + ti) * 128 + (tj0 + tj); // global position
    float4 wreg[13];
    const float4* wv = (const float4*)(wp + OFF_W1 + p * 52);
#pragma unroll
    for (int t = 0; t < 13; ++t) wreg[t] = __ldg(wv + t);
    const float* wf = (const float*)wreg;
    const float bias = __ldg(b1 + p);
    __syncthreads();

    // two batches at a time -> 2 independent FMA chains for ILP
#pragma unroll
    for (int bb = 0; bb < 8; bb += 2) {
        float acc0 = bias, acc1 = bias;
#pragma unroll
        for (int u = 0; u < 7; ++u)
#pragma unroll
            for (int v = 0; v < 7; ++v) {
                float wv_ = wf[u * 7 + v];
                acc0 = fmaf(sm[bb][ti + u][tj + v], wv_, acc0);
                acc1 = fmaf(sm[bb + 1][ti + u][tj + v], wv_, acc1);
            }
        out[(bg * 8 + bb) * 16384 + p] = fmaxf(acc0, 0.0f);
        out[(bg * 8 + bb + 1) * 16384 + p] = fmaxf(acc1, 0.0f);
    }
}

// ---------------------------------------------------------------------------
// Mega kernel pieces (1024 threads)
// ---------------------------------------------------------------------------
__device__ __forceinline__ float2 block_stats2(float s, float ss) {
    __shared__ float r0[32], r1[32];
    int tid = threadIdx.x, wid = tid >> 5, lid = tid & 31;
#pragma unroll
    for (int o = 16; o; o >>= 1) {
        s += __shfl_down_sync(0xFFFFFFFFu, s, o);
        ss += __shfl_down_sync(0xFFFFFFFFu, ss, o);
    }
    if (lid == 0) { r0[wid] = s; r1[wid] = ss; }
    __syncthreads();
    if (wid == 0) {
        s = r0[lid];
        ss = r1[lid];
#pragma unroll
        for (int o = 16; o; o >>= 1) {
            s += __shfl_down_sync(0xFFFFFFFFu, s, o);
            ss += __shfl_down_sync(0xFFFFFFFFu, ss, o);
        }
        if (lid == 0) { r0[0] = s; r1[0] = ss; }
    }
    __syncthreads();
    float2 res = make_float2(r0[0], r1[0]);
    __syncthreads();
    return res;
}

// locally-connected conv + relu from smem src to smem dst; weights vec4-packed
template <int H, int K, int PAD, int WS, int NT>
__device__ __forceinline__ void conv_stage(const float* __restrict__ src, float* __restrict__ dst,
                                           const float* __restrict__ wp, const float* __restrict__ bias) {
    constexpr int N = H * H;
    constexpr int NV = (K * K + 3) / 4;
    for (int p = threadIdx.x; p < N; p += NT) {
        int i = p / H, j = p - i * H;
        float4 wreg[NV];
        const float4* wv = (const float4*)(wp + p * WS);
#pragma unroll
        for (int t = 0; t < NV; ++t) wreg[t] = __ldg(wv + t);
        const float* wf = (const float*)wreg;
        float acc = __ldg(bias + p);
#pragma unroll
        for (int u = 0; u < K; ++u) {
            int ii = i + u - PAD;
            if ((unsigned)ii < (unsigned)H) {
#pragma unroll
                for (int v = 0; v < K; ++v) {
                    int jj = j + v - PAD;
                    float xv = ((unsigned)jj < (unsigned)H) ? src[ii * H + jj] : 0.0f;
                    acc = fmaf(xv, wf[u * K + v], acc);
                }
            }
        }
        dst[p] = fmaxf(acc, 0.0f);
    }
}

// ---------------------------------------------------------------------------
// Mega kernel: block per sample (grid=64, 1024 threads).
// LN1+pool (from conv1 global) -> conv2 -> LN2 -> conv3 -> LN3+pool
// -> conv4 -> LN4 -> conv5 -> LN5+pool -> conv6 -> LN6 -> h[256]
// ---------------------------------------------------------------------------
#define MT 1024
__global__ void __launch_bounds__(MT) mega_kernel(
    const float* __restrict__ c1, const float* __restrict__ g1, const float* __restrict__ be1,
    const float* __restrict__ wp,
    const float* __restrict__ b2, const float* __restrict__ g2, const float* __restrict__ be2,
    const float* __restrict__ b3, const float* __restrict__ g3, const float* __restrict__ be3,
    const float* __restrict__ b4, const float* __restrict__ g4, const float* __restrict__ be4,
    const float* __restrict__ b5, const float* __restrict__ g5, const float* __restrict__ be5,
    const float* __restrict__ b6, const float* __restrict__ g6, const float* __restrict__ be6,
    float* __restrict__ hout) {
    __shared__ float A[4096], B[4096];
    const int tid = threadIdx.x;
    const int b = blockIdx.x;
    const float* ip = c1 + b * 16384;

    // --- LN1 stats over conv1 output (128x128) ---
    float s = 0.0f, ss = 0.0f;
    for (int i = tid; i < 16384; i += MT) { float v = ip[i]; s += v; ss += v * v; }
    float2 st = block_stats2(s, ss);
    float mu = st.x * (1.0f / 16384.0f);
    float rstd = rsqrtf(st.y * (1.0f / 16384.0f) - mu * mu + 1e-5f);
    // normalize + 2x2 pool -> A (64x64)
    for (int p = tid; p < 4096; p += MT) {
        int io = p >> 6, jo = p & 63;
        float m = -CUDART_INF_F;
#pragma unroll
        for (int di = 0; di < 2; ++di)
#pragma unroll
            for (int dj = 0; dj < 2; ++dj) {
                int q = (2 * io + di) * 128 + 2 * jo + dj;
                float v = (ip[q] - mu) * rstd * __ldg(g1 + q) + __ldg(be1 + q);
                m = fmaxf(m, v);
            }
        A[p] = m;
    }
    __syncthreads();

    // --- conv2 (64x64, K=5) A -> B ---
    conv_stage<64, 5, 2, 32, MT>(A, B, wp + OFF_W2, b2);
    __syncthreads();
    // --- LN2 in-place on B ---
    s = ss = 0.0f;
    for (int p = tid; p < 4096; p += MT) { float v = B[p]; s += v; ss += v * v; }
    st = block_stats2(s, ss);
    mu = st.x * (1.0f / 4096.0f);
    rstd = rsqrtf(st.y * (1.0f / 4096.0f) - mu * mu + 1e-5f);
    for (int p = tid; p < 4096; p += MT) B[p] = (B[p] - mu) * rstd * __ldg(g2 + p) + __ldg(be2 + p);
    __syncthreads();

    // --- conv3 (64x64, K=5) B -> A ---
    conv_stage<64, 5, 2, 32, MT>(B, A, wp + OFF_W3, b3);
    __syncthreads();
    // --- LN3 + pool: A (64x64) -> B (32x32) ---
    s = ss = 0.0f;
    for (int p = tid; p < 4096; p += MT) { float v = A[p]; s += v; ss += v * v; }
    st = block_stats2(s, ss);
    mu = st.x * (1.0f / 4096.0f);
    rstd = rsqrtf(st.y * (1.0f / 4096.0f) - mu * mu + 1e-5f);
    for (int p = tid; p < 1024; p += MT) {
        int io = p >> 5, jo = p & 31;
        float m = -CUDART_INF_F;
#pragma unroll
        for (int di = 0; di < 2; ++di)
#pragma unroll
            for (int dj = 0; dj < 2; ++dj) {
                int q = (2 * io + di) * 64 + 2 * jo + dj;
                float v = (A[q] - mu) * rstd * __ldg(g3 + q) + __ldg(be3 + q);
                m = fmaxf(m, v);
            }
        B[p] = m;
    }
    __syncthreads();

    // --- conv4 (32x32, K=3) B -> A ---
    conv_stage<32, 3, 1, 12, MT>(B, A, wp + OFF_W4, b4);
    __syncthreads();
    // --- LN4 in-place on A (1024) ---
    s = ss = 0.0f;
    for (int p = tid; p < 1024; p += MT) { float v = A[p]; s += v; ss += v * v; }
    st = block_stats2(s, ss);
    mu = st.x * (1.0f / 1024.0f);
    rstd = rsqrtf(st.y * (1.0f / 1024.0f) - mu * mu + 1e-5f);
    for (int p = tid; p < 1024; p += MT) A[p] = (A[p] - mu) * rstd * __ldg(g4 + p) + __ldg(be4 + p);
    __syncthreads();

    // --- conv5 (32x32, K=3) A -> B ---
    conv_stage<32, 3, 1, 12, MT>(A, B, wp + OFF_W5, b5);
    __syncthreads();
    // --- LN5 + pool: B (32x32) -> A (16x16) ---
    s = ss = 0.0f;
    for (int p = tid; p < 1024; p += MT) { float v = B[p]; s += v; ss += v * v; }
    st = block_stats2(s, ss);
    mu = st.x * (1.0f / 1024.0f);
    rstd = rsqrtf(st.y * (1.0f / 1024.0f) - mu * mu + 1e-5f);
    for (int p = tid; p < 256; p += MT) {
        int io = p >> 4, jo = p & 15;
        float m = -CUDART_INF_F;
#pragma unroll
        for (int di = 0; di < 2; ++di)
#pragma unroll
            for (int dj = 0; dj < 2; ++dj) {
                int q = (2 * io + di) * 32 + 2 * jo + dj;
                float v = (B[q] - mu) * rstd * __ldg(g5 + q) + __ldg(be5 + q);
                m = fmaxf(m, v);
            }
        A[p] = m;
    }
    __syncthreads();

    // --- conv6 (16x16, K=3) A -> B ---
    conv_stage<16, 3, 1, 12, MT>(A, B, wp + OFF_W6, b6);
    __syncthreads();
    // --- LN6 over B (256) -> h ---
    s = ss = 0.0f;
    for (int p = tid; p < 256; p += MT) { float v = B[p]; s += v; ss += v * v; }
    st = block_stats2(s, ss);
    mu = st.x * (1.0f / 256.0f);
    rstd = rsqrtf(st.y * (1.0f / 256.0f) - mu * mu + 1e-5f);
    for (int p = tid; p < 256; p += MT)
        hout[b * 256 + p] = (B[p] - mu) * rstd * __ldg(g6 + p) + __ldg(be6 + p);
}

// ---------------------------------------------------------------------------
// FC: logits[64,1024] = h[64,256] @ fcw.T + fcb.
// Grid = (32 col-tiles of 32 outputs, 8 row-groups of 8 rows), 256 threads.
// Warp per output (4 outputs per warp) with h cached in registers.
// ---------------------------------------------------------------------------
__global__ void __launch_bounds__(256) fc_kernel(const float* __restrict__ h,
                                                 const float* __restrict__ fcw,
                                                 const float* __restrict__ fcb,
                                                 float* __restrict__ logits) {
    __shared__ float hs[8 * 256];
    const int ct = blockIdx.x, rg = blockIdx.y;
    const int tid = threadIdx.x, wid = tid >> 5, lid = tid & 31;

    for (int e = tid; e < 2048; e += 256) hs[e] = h[rg * 2048 + e];
    __syncthreads();

    float hr[8][8];
#pragma unroll
    for (int r = 0; r < 8; ++r)
#pragma unroll
        for (int c = 0; c < 8; ++c) hr[r][c] = hs[r * 256 + lid * 8 + c];

    const int obase = ct * 32 + wid * 4;
#pragma unroll
    for (int t = 0; t < 4; ++t) {
        int o = obase + t;
        const float4* wr = (const float4*)(fcw + o * 256 + lid * 8);
        float4 wa = __ldg(wr), wb = __ldg(wr + 1);
        float a[8];
#pragma unroll
        for (int r = 0; r < 8; ++r) {
            a[r] = hr[r][0] * wa.x + hr[r][1] * wa.y + hr[r][2] * wa.z + hr[r][3] * wa.w
                 + hr[r][4] * wb.x + hr[r][5] * wb.y + hr[r][6] * wb.z + hr[r][7] * wb.w;
        }
#pragma unroll
        for (int r = 0; r < 8; ++r)
#pragma unroll
            for (int off = 16; off; off >>= 1) a[r] += __shfl_down_sync(0xFFFFFFFFu, a[r], off);
        if (lid == 0) {
            float bo = __ldg(fcb + o);
#pragma unroll
            for (int r = 0; r < 8; ++r) logits[(rg * 8 + r) * 1024 + o] = a[r] + bo;
        }
    }
}

// ---------------------------------------------------------------------------
// Softmax over 1024 per row. Grid=64, 256 threads.
// ---------------------------------------------------------------------------
__global__ void __launch_bounds__(256) softmax_kernel(const float* __restrict__ logits,
                                                      float* __restrict__ out) {
    __shared__ float sm[1024];
    __shared__ float red[8];
    const int b = blockIdx.x, tid = threadIdx.x, wid = tid >> 5, lid = tid & 31;
    const float* row = logits + b * 1024;

    float mx = -CUDART_INF_F;
    for (int i = tid; i < 1024; i += 256) { float v = row[i]; sm[i] = v; mx = fmaxf(mx, v); }
#pragma unroll
    for (int o = 16; o; o >>= 1) mx = fmaxf(mx, __shfl_xor_sync(0xFFFFFFFFu, mx, o));
    if (lid == 0) red[wid] = mx;
    __syncthreads();
    mx = red[0];
#pragma unroll
    for (int w = 1; w < 8; ++w) mx = fmaxf(mx, red[w]);

    float ps = 0.0f;
    for (int i = tid; i < 1024; i += 256) { float e = __expf(sm[i] - mx); sm[i] = e; ps += e; }
#pragma unroll
    for (int o = 16; o; o >>= 1) ps += __shfl_xor_sync(0xFFFFFFFFu, ps, o);
    __syncthreads();
    if (lid == 0) red[wid] = ps;
    __syncthreads();
    float tot = 0.0f;
#pragma unroll
    for (int w = 0; w < 8; ++w) tot += red[w];
    float inv = 1.0f / tot;
    for (int i = tid; i < 1024; i += 256) out[b * 1024 + i] = sm[i] * inv;
}

// ---------------------------------------------------------------------------
extern "C" void kernel_launch(void* const* d_in, const int* in_sizes, int n_in,
                              void* d_out, int out_size) {
    (void)in_sizes; (void)n_in; (void)out_size;

    const float* x = (const float*)d_in[0];
    const float* w[7];
    const float* bi[7];
    const float* gg[7];
    const float* bb[7];
    for (int L = 1; L <= 6; ++L) {
        w[L]  = (const float*)d_in[1 + 4 * (L - 1) + 0];
        bi[L] = (const float*)d_in[1 + 4 * (L - 1) + 1];
        gg[L] = (const float*)d_in[1 + 4 * (L - 1) + 2];
        bb[L] = (const float*)d_in[1 + 4 * (L - 1) + 3];
    }
    const float* fcw = (const float*)d_in[25];
    const float* fcb = (const float*)d_in[26];
    float* out = (float*)d_out;

    float *c1, *h, *lg, *wp;
    cudaGetSymbolAddress((void**)&c1, g_conv1);
    cudaGetSymbolAddress((void**)&h, g_h);
    cudaGetSymbolAddress((void**)&lg, g_logits);
    cudaGetSymbolAddress((void**)&wp, g_wpack);

    repack_kernel<<<256, 256>>>(w[1], w[2], w[3], w[4], w[5], w[6], wp);
    conv1_kernel<<<dim3(64, 8), 256>>>(x, wp, bi[1], c1);
    mega_kernel<<<64, MT>>>(c1, gg[1], bb[1], wp,
                            bi[2], gg[2], bb[2],
                            bi[3], gg[3], bb[3],
                            bi[4], gg[4], bb[4],
                            bi[5], gg[5], bb[5],
                            bi[6], gg[6], bb[6],
                            h);
    fc_kernel<<<dim3(32, 8), 256>>>(h, fcw, fcb, lg);
    softmax_kernel<<<64, 256>>>(lg, out);
}